// round 10
// baseline (speedup 1.0000x reference)
#include <cuda_runtime.h>
#include <cuda_bf16.h>
#include <cstdint>

#define N_NODES 100000
#define N_EDGES 3200000
#define IN_FEATS 1433
#define HID 16
#define OUT 7
#define NBLK 391  // ceil(100000/256)

// ---------------- device scratch ----------------
__device__ int   g_is64;
__device__ int   g_deg_out[N_NODES];
__device__ int   g_deg_in[N_NODES];
__device__ float g_norm_src[N_NODES];
__device__ float g_norm_dst[N_NODES];
__device__ int   g_row_start[N_NODES];
__device__ int   g_cursor[N_NODES];
__device__ int   g_csr_src[N_EDGES];
__device__ int   g_part[512];
__device__ __align__(128) float g_x1[N_NODES * 16];
__device__ __align__(128) float g_x2[N_NODES * 8];

// ---------------- helpers ----------------
#define FMA2(d, a, b) asm("fma.rn.f32x2 %0, %1, %2, %3;" : "=l"(d) : "l"(a), "l"(b), "l"(d))
#define ADD2(d, a, b) asm("add.rn.f32x2 %0, %1, %2;" : "=l"(d) : "l"(a), "l"(b))

__device__ __forceinline__ unsigned long long pack2(float a, float b) {
    unsigned long long r;
    asm("mov.b64 %0, {%1, %2};" : "=l"(r) : "r"(__float_as_uint(a)), "r"(__float_as_uint(b)));
    return r;
}

// ---------------- kernels ----------------

// Zero degree counters + detect int64 vs int32 edge buffer.
__global__ void init_kernel(const int* ei_words) {
    int i = blockIdx.x * blockDim.x + threadIdx.x;
    if (i < N_NODES) { g_deg_out[i] = 0; g_deg_in[i] = 0; }
    if (i == 0) {
        int all_zero = 1;
        for (int t = 0; t < 64; t++)
            if (ei_words[2 * t + 1] != 0) { all_zero = 0; break; }
        g_is64 = all_zero;
    }
}

// Degree histograms, 2 edges per thread (vector loads).
__global__ void edge_kernel(const void* ei_raw) {
    int e0 = (blockIdx.x * blockDim.x + threadIdx.x) * 2;
    if (e0 >= N_EDGES) return;
    int s0, s1, d0, d1;
    if (g_is64) {
        const longlong2 sv = *(const longlong2*)((const long long*)ei_raw + e0);
        const longlong2 dv = *(const longlong2*)((const long long*)ei_raw + N_EDGES + e0);
        s0 = (int)sv.x; s1 = (int)sv.y; d0 = (int)dv.x; d1 = (int)dv.y;
    } else {
        const int2 sv = *(const int2*)((const int*)ei_raw + e0);
        const int2 dv = *(const int2*)((const int*)ei_raw + N_EDGES + e0);
        s0 = sv.x; s1 = sv.y; d0 = dv.x; d1 = dv.y;
    }
    atomicAdd(&g_deg_out[s0], 1);
    atomicAdd(&g_deg_out[s1], 1);
    atomicAdd(&g_deg_in[d0], 1);
    atomicAdd(&g_deg_in[d1], 1);
}

// scan pass 1: per-block sums of deg_in
__global__ void scan1_kernel() {
    __shared__ int s[256];
    int tid = threadIdx.x;
    int i = blockIdx.x * 256 + tid;
    s[tid] = (i < N_NODES) ? g_deg_in[i] : 0;
    __syncthreads();
    for (int off = 128; off > 0; off >>= 1) {
        if (tid < off) s[tid] += s[tid + off];
        __syncthreads();
    }
    if (tid == 0) g_part[blockIdx.x] = s[0];
}

// scan pass 2+3 fused: each block redundantly reduces its prefix of g_part,
// then does the intra-block scan + row_start/cursor/norm writes.
__global__ void scan3_kernel() {
    __shared__ int s[256];
    __shared__ int sp[256];
    __shared__ int sbase;
    int tid = threadIdx.x;

    // base = sum of g_part[0 .. blockIdx.x)
    int p = 0;
    for (int t = tid; t < blockIdx.x; t += 256) p += g_part[t];
    sp[tid] = p;
    __syncthreads();
    for (int off = 128; off > 0; off >>= 1) {
        if (tid < off) sp[tid] += sp[tid + off];
        __syncthreads();
    }
    if (tid == 0) sbase = sp[0];
    __syncthreads();

    int i = blockIdx.x * 256 + tid;
    int v = (i < N_NODES) ? g_deg_in[i] : 0;
    s[tid] = v;
    __syncthreads();
    for (int off = 1; off < 256; off <<= 1) {
        int t = (tid >= off) ? s[tid - off] : 0;
        __syncthreads();
        s[tid] += t;
        __syncthreads();
    }
    if (i < N_NODES) {
        int rs = sbase + s[tid] - v;
        g_row_start[i] = rs;
        g_cursor[i] = rs;
        int dout = g_deg_out[i]; if (dout < 1) dout = 1;
        int din  = g_deg_in[i];  if (din  < 1) din  = 1;
        g_norm_src[i] = rsqrtf((float)dout);
        g_norm_dst[i] = rsqrtf((float)din);
    }
}

// Fill CSR (grouped by dst, storing src ids), 2 edges per thread.
__global__ void fill_kernel(const void* ei_raw) {
    int e0 = (blockIdx.x * blockDim.x + threadIdx.x) * 2;
    if (e0 >= N_EDGES) return;
    int s0, s1, d0, d1;
    if (g_is64) {
        const longlong2 sv = *(const longlong2*)((const long long*)ei_raw + e0);
        const longlong2 dv = *(const longlong2*)((const long long*)ei_raw + N_EDGES + e0);
        s0 = (int)sv.x; s1 = (int)sv.y; d0 = (int)dv.x; d1 = (int)dv.y;
    } else {
        const int2 sv = *(const int2*)((const int*)ei_raw + e0);
        const int2 dv = *(const int2*)((const int*)ei_raw + N_EDGES + e0);
        s0 = sv.x; s1 = sv.y; d0 = dv.x; d1 = dv.y;
    }
    int p0 = atomicAdd(&g_cursor[d0], 1);
    g_csr_src[p0] = s0;
    int p1 = atomicAdd(&g_cursor[d1], 1);
    g_csr_src[p1] = s1;
}

// GEMM1: x1[n, :] = norm_src[n] * (feat[n, :] @ W1)
// 4 nodes/warp, swizzled conflict-free W1 in smem, f32x2 FMA,
// 2-deep feat prefetch, merged transpose-reduce.
__global__ void __launch_bounds__(512) gemm1_kernel(const float* __restrict__ feat,
                                                    const float* __restrict__ W1) {
    extern __shared__ float sW1[];  // 1433*16, swizzled
    for (int i = threadIdx.x; i < IN_FEATS * 16; i += blockDim.x) {
        int k = i >> 4, c = i & 15;
        int r = k + (k >> 2);
        int pp = ((c >> 2) + r) & 3;
        sW1[(k << 4) + (pp << 2) + (c & 3)] = W1[i];
    }
    __syncthreads();

    const int lane = threadIdx.x & 31;
    const int rv = __brev(lane) >> 27;  // bit-reversed lane = final value index
    const int warp_global = blockIdx.x * (blockDim.x >> 5) + (threadIdx.x >> 5);
    const int nwarps = gridDim.x * (blockDim.x >> 5);

    for (int g = warp_global; g < N_NODES / 4; g += nwarps) {
        const int n0 = g * 4;
        const float* __restrict__ f0 = feat + (size_t)n0 * IN_FEATS;

        // v[j*8+p] = f32x2 partial for node j, channels (2p, 2p+1)
        unsigned long long v[32];
        #pragma unroll
        for (int i = 0; i < 32; i++) v[i] = 0ull;

        float fa[4], fb[4], fc[4];
        #pragma unroll
        for (int j = 0; j < 4; j++) {
            fa[j] = __ldg(f0 + (size_t)j * IN_FEATS + lane);
            fb[j] = __ldg(f0 + (size_t)j * IN_FEATS + lane + 32);
        }

        for (int k = lane; k < IN_FEATS; k += 32) {
            const int k2 = k + 64;
            if (k2 < IN_FEATS) {
                #pragma unroll
                for (int j = 0; j < 4; j++)
                    fc[j] = __ldg(f0 + (size_t)j * IN_FEATS + k2);
            } else {
                #pragma unroll
                for (int j = 0; j < 4; j++) fc[j] = 0.0f;
            }

            const int kb = k << 4;
            const int r = k + (k >> 2);
            const ulonglong2 u0 = *(const ulonglong2*)&sW1[kb + (((0 + r) & 3) << 2)];
            const ulonglong2 u1 = *(const ulonglong2*)&sW1[kb + (((1 + r) & 3) << 2)];
            const ulonglong2 u2 = *(const ulonglong2*)&sW1[kb + (((2 + r) & 3) << 2)];
            const ulonglong2 u3 = *(const ulonglong2*)&sW1[kb + (((3 + r) & 3) << 2)];

            #pragma unroll
            for (int j = 0; j < 4; j++) {
                const unsigned long long ff = pack2(fa[j], fa[j]);
                FMA2(v[j * 8 + 0], u0.x, ff);
                FMA2(v[j * 8 + 1], u0.y, ff);
                FMA2(v[j * 8 + 2], u1.x, ff);
                FMA2(v[j * 8 + 3], u1.y, ff);
                FMA2(v[j * 8 + 4], u2.x, ff);
                FMA2(v[j * 8 + 5], u2.y, ff);
                FMA2(v[j * 8 + 6], u3.x, ff);
                FMA2(v[j * 8 + 7], u3.y, ff);
            }
            #pragma unroll
            for (int j = 0; j < 4; j++) { fa[j] = fb[j]; fb[j] = fc[j]; }
        }

        // Merged transpose-reduce: lane ends holding value index bitrev(lane).
        #pragma unroll
        for (int round = 0; round < 5; round++) {
            const int m = 1 << round;
            const int h = 16 >> round;
            const bool up = (lane & m) != 0;
            #pragma unroll
            for (int i = 0; i < h; i++) {
                unsigned long long send, keep;
                if (up) { send = v[i];     keep = v[i + h]; }
                else    { send = v[i + h]; keep = v[i]; }
                unsigned long long recv = __shfl_xor_sync(0xffffffffu, send, m);
                ADD2(v[i], keep, recv);
            }
        }

        const int n = n0 + (rv >> 3);
        const int c0 = (rv & 7) << 1;
        unsigned lo, hi;
        asm("mov.b64 {%0, %1}, %2;" : "=r"(lo), "=r"(hi) : "l"(v[0]));
        const float ns = g_norm_src[n];
        float2 o;
        o.x = __uint_as_float(lo) * ns;
        o.y = __uint_as_float(hi) * ns;
        *(float2*)&g_x1[(size_t)n * 16 + c0] = o;
    }
}

// Gather layer 1 (CSR) fused with relu + bias + GEMM2 epilogue.
// One warp per dst node; lane = (edge-slot, quad): one LDG.128 covers 8 edges.
__global__ void gather1_kernel(const float* __restrict__ b1,
                               const float* __restrict__ W2) {
    __shared__ float sW2[16 * 8];  // [k][c2], col 7 zero-padded
    __shared__ float sb1[16];
    for (int i = threadIdx.x; i < 16 * 8; i += blockDim.x) {
        int k = i >> 3, c2 = i & 7;
        sW2[i] = (c2 < OUT) ? W2[k * OUT + c2] : 0.0f;
    }
    if (threadIdx.x < 16) sb1[threadIdx.x] = b1[threadIdx.x];
    __syncthreads();

    const int n = (blockIdx.x * blockDim.x + threadIdx.x) >> 5;
    if (n >= N_NODES) return;
    const int lane = threadIdx.x & 31;
    const int q = lane & 3;       // quad: channels 4q..4q+3
    const int eoff = lane >> 2;   // edge slot 0..7

    const int start = g_row_start[n];
    const int end = start + g_deg_in[n];

    float4 acc = make_float4(0.f, 0.f, 0.f, 0.f);
    for (int e = start + eoff; e < end; e += 8) {
        const int s = g_csr_src[e];
        const float4 v = *(const float4*)&g_x1[(size_t)s * 16 + q * 4];
        acc.x += v.x; acc.y += v.y; acc.z += v.z; acc.w += v.w;
    }
    #pragma unroll
    for (int m = 4; m <= 16; m <<= 1) {
        acc.x += __shfl_xor_sync(0xffffffffu, acc.x, m);
        acc.y += __shfl_xor_sync(0xffffffffu, acc.y, m);
        acc.z += __shfl_xor_sync(0xffffffffu, acc.z, m);
        acc.w += __shfl_xor_sync(0xffffffffu, acc.w, m);
    }
    // every lane now holds the 4-channel sum for quad (lane&3)

    const float nd = g_norm_dst[n];
    const int c2 = lane & 7;
    float acc2 = 0.0f;
    #pragma unroll
    for (int k = 0; k < 16; k++) {
        const int srcq = k >> 2;
        const int comp = k & 3;
        const float t = (comp == 0) ? acc.x : (comp == 1) ? acc.y
                      : (comp == 2) ? acc.z : acc.w;
        const float sum_k = __shfl_sync(0xffffffffu, t, srcq);
        const float hk = fmaxf(sum_k * nd + sb1[k], 0.0f);
        acc2 += hk * sW2[k * 8 + c2];
    }
    if (lane < 8) {
        const float ns = g_norm_src[n];
        g_x2[(size_t)n * 8 + lane] = (lane < OUT) ? acc2 * ns : 0.0f;
    }
}

// Gather layer 2 fused with final bias. One warp per dst node;
// lane = (edge-slot, half): one LDG.128 covers 16 edges.
__global__ void gather2_kernel(const float* __restrict__ b2,
                               float* __restrict__ out) {
    __shared__ float sb2[8];
    if (threadIdx.x < 8) sb2[threadIdx.x] = (threadIdx.x < OUT) ? b2[threadIdx.x] : 0.0f;
    __syncthreads();

    const int n = (blockIdx.x * blockDim.x + threadIdx.x) >> 5;
    if (n >= N_NODES) return;
    const int lane = threadIdx.x & 31;
    const int half = lane & 1;    // channels 4*half..4*half+3
    const int eoff = lane >> 1;   // edge slot 0..15

    const int start = g_row_start[n];
    const int end = start + g_deg_in[n];

    float4 acc = make_float4(0.f, 0.f, 0.f, 0.f);
    for (int e = start + eoff; e < end; e += 16) {
        const int s = g_csr_src[e];
        const float4 v = *(const float4*)&g_x2[(size_t)s * 8 + half * 4];
        acc.x += v.x; acc.y += v.y; acc.z += v.z; acc.w += v.w;
    }
    #pragma unroll
    for (int m = 2; m <= 16; m <<= 1) {
        acc.x += __shfl_xor_sync(0xffffffffu, acc.x, m);
        acc.y += __shfl_xor_sync(0xffffffffu, acc.y, m);
        acc.z += __shfl_xor_sync(0xffffffffu, acc.z, m);
        acc.w += __shfl_xor_sync(0xffffffffu, acc.w, m);
    }
    // every lane holds the 4-channel sum for half (lane&1)

    if (lane < 2) {
        const float nd = g_norm_dst[n];
        float* o = out + (size_t)n * OUT;
        if (lane == 0) {
            o[0] = acc.x * nd + sb2[0];
            o[1] = acc.y * nd + sb2[1];
            o[2] = acc.z * nd + sb2[2];
            o[3] = acc.w * nd + sb2[3];
        } else {
            o[4] = acc.x * nd + sb2[4];
            o[5] = acc.y * nd + sb2[5];
            o[6] = acc.z * nd + sb2[6];
        }
    }
}

// ---------------- launch ----------------
extern "C" void kernel_launch(void* const* d_in, const int* in_sizes, int n_in,
                              void* d_out, int out_size) {
    const float* feat = (const float*)d_in[0];
    const void*  ei   = d_in[1];
    const float* W1   = (const float*)d_in[2];
    const float* b1   = (const float*)d_in[3];
    const float* W2   = (const float*)d_in[4];
    const float* b2   = (const float*)d_in[5];
    float* out = (float*)d_out;

    const int smem1 = IN_FEATS * 16 * sizeof(float);  // 91712 bytes
    cudaFuncSetAttribute(gemm1_kernel, cudaFuncAttributeMaxDynamicSharedMemorySize, smem1);

    init_kernel<<<NBLK, 256>>>((const int*)ei);
    edge_kernel<<<(N_EDGES / 2 + 255) / 256, 256>>>(ei);
    scan1_kernel<<<NBLK, 256>>>();
    scan3_kernel<<<NBLK, 256>>>();
    fill_kernel<<<(N_EDGES / 2 + 255) / 256, 256>>>(ei);
    gemm1_kernel<<<148, 512, smem1>>>(feat, W1);
    gather1_kernel<<<(N_NODES * 32 + 255) / 256, 256>>>(b1, W2);
    gather2_kernel<<<(N_NODES * 32 + 255) / 256, 256>>>(b2, out);
}

// round 13
// speedup vs baseline: 1.0958x; 1.0958x over previous
#include <cuda_runtime.h>
#include <cuda_bf16.h>
#include <cstdint>

#define N_NODES 100000
#define N_EDGES 3200000
#define IN_FEATS 1433
#define HID 16
#define OUT 7
#define NBLK 391  // ceil(100000/256)

// ---------------- device scratch ----------------
__device__ int   g_is64;
__device__ int   g_deg_out[N_NODES];
__device__ int   g_deg_in[N_NODES];
__device__ float g_norm_src[N_NODES];
__device__ float g_norm_dst[N_NODES];
__device__ int   g_row_start[N_NODES];
__device__ int   g_cursor[N_NODES];
__device__ int   g_csr_src[N_EDGES];
__device__ int   g_part[512];
__device__ __align__(128) float g_x1[N_NODES * 16];
__device__ __align__(128) float g_x2[N_NODES * 8];

// ---------------- helpers ----------------
#define FMA2(d, a, b) asm("fma.rn.f32x2 %0, %1, %2, %3;" : "=l"(d) : "l"(a), "l"(b), "l"(d))
#define ADD2(d, a, b) asm("add.rn.f32x2 %0, %1, %2;" : "=l"(d) : "l"(a), "l"(b))

__device__ __forceinline__ unsigned long long pack2(float a, float b) {
    unsigned long long r;
    asm("mov.b64 %0, {%1, %2};" : "=l"(r) : "r"(__float_as_uint(a)), "r"(__float_as_uint(b)));
    return r;
}

// ---------------- kernels ----------------

// Zero degree counters + detect int64 vs int32 edge buffer.
__global__ void init_kernel(const int* ei_words) {
    int i = blockIdx.x * blockDim.x + threadIdx.x;
    if (i < N_NODES) { g_deg_out[i] = 0; g_deg_in[i] = 0; }
    if (i == 0) {
        int all_zero = 1;
        for (int t = 0; t < 64; t++)
            if (ei_words[2 * t + 1] != 0) { all_zero = 0; break; }
        g_is64 = all_zero;
    }
}

// Degree histograms, 2 edges per thread (vector loads).
__global__ void edge_kernel(const void* ei_raw) {
    int e0 = (blockIdx.x * blockDim.x + threadIdx.x) * 2;
    if (e0 >= N_EDGES) return;
    int s0, s1, d0, d1;
    if (g_is64) {
        const longlong2 sv = *(const longlong2*)((const long long*)ei_raw + e0);
        const longlong2 dv = *(const longlong2*)((const long long*)ei_raw + N_EDGES + e0);
        s0 = (int)sv.x; s1 = (int)sv.y; d0 = (int)dv.x; d1 = (int)dv.y;
    } else {
        const int2 sv = *(const int2*)((const int*)ei_raw + e0);
        const int2 dv = *(const int2*)((const int*)ei_raw + N_EDGES + e0);
        s0 = sv.x; s1 = sv.y; d0 = dv.x; d1 = dv.y;
    }
    atomicAdd(&g_deg_out[s0], 1);
    atomicAdd(&g_deg_out[s1], 1);
    atomicAdd(&g_deg_in[d0], 1);
    atomicAdd(&g_deg_in[d1], 1);
}

// norm_src only (unblocks gemm1 on the side stream).
__global__ void norm_src_kernel() {
    int i = blockIdx.x * blockDim.x + threadIdx.x;
    if (i >= N_NODES) return;
    int dout = g_deg_out[i]; if (dout < 1) dout = 1;
    g_norm_src[i] = rsqrtf((float)dout);
}

// scan pass 1: per-block sums of deg_in
__global__ void scan1_kernel() {
    __shared__ int s[256];
    int tid = threadIdx.x;
    int i = blockIdx.x * 256 + tid;
    s[tid] = (i < N_NODES) ? g_deg_in[i] : 0;
    __syncthreads();
    for (int off = 128; off > 0; off >>= 1) {
        if (tid < off) s[tid] += s[tid + off];
        __syncthreads();
    }
    if (tid == 0) g_part[blockIdx.x] = s[0];
}

// scan pass 2+3 fused: each block redundantly reduces its prefix of g_part,
// then does the intra-block scan + row_start/cursor/norm_dst writes.
__global__ void scan3_kernel() {
    __shared__ int s[256];
    __shared__ int sp[256];
    __shared__ int sbase;
    int tid = threadIdx.x;

    int p = 0;
    for (int t = tid; t < blockIdx.x; t += 256) p += g_part[t];
    sp[tid] = p;
    __syncthreads();
    for (int off = 128; off > 0; off >>= 1) {
        if (tid < off) sp[tid] += sp[tid + off];
        __syncthreads();
    }
    if (tid == 0) sbase = sp[0];
    __syncthreads();

    int i = blockIdx.x * 256 + tid;
    int v = (i < N_NODES) ? g_deg_in[i] : 0;
    s[tid] = v;
    __syncthreads();
    for (int off = 1; off < 256; off <<= 1) {
        int t = (tid >= off) ? s[tid - off] : 0;
        __syncthreads();
        s[tid] += t;
        __syncthreads();
    }
    if (i < N_NODES) {
        int rs = sbase + s[tid] - v;
        g_row_start[i] = rs;
        g_cursor[i] = rs;
        int din = g_deg_in[i]; if (din < 1) din = 1;
        g_norm_dst[i] = rsqrtf((float)din);
    }
}

// Fill CSR (grouped by dst, storing src ids), 2 edges per thread.
__global__ void fill_kernel(const void* ei_raw) {
    int e0 = (blockIdx.x * blockDim.x + threadIdx.x) * 2;
    if (e0 >= N_EDGES) return;
    int s0, s1, d0, d1;
    if (g_is64) {
        const longlong2 sv = *(const longlong2*)((const long long*)ei_raw + e0);
        const longlong2 dv = *(const longlong2*)((const long long*)ei_raw + N_EDGES + e0);
        s0 = (int)sv.x; s1 = (int)sv.y; d0 = (int)dv.x; d1 = (int)dv.y;
    } else {
        const int2 sv = *(const int2*)((const int*)ei_raw + e0);
        const int2 dv = *(const int2*)((const int*)ei_raw + N_EDGES + e0);
        s0 = sv.x; s1 = sv.y; d0 = dv.x; d1 = dv.y;
    }
    int p0 = atomicAdd(&g_cursor[d0], 1);
    g_csr_src[p0] = s0;
    int p1 = atomicAdd(&g_cursor[d1], 1);
    g_csr_src[p1] = s1;
}

// GEMM1: x1[n, :] = norm_src[n] * (feat[n, :] @ W1)
// 4 nodes/warp, swizzled conflict-free W1 in smem, f32x2 FMA,
// 2-deep feat prefetch, merged transpose-reduce.
__global__ void __launch_bounds__(512) gemm1_kernel(const float* __restrict__ feat,
                                                    const float* __restrict__ W1) {
    extern __shared__ float sW1[];  // 1433*16, swizzled
    for (int i = threadIdx.x; i < IN_FEATS * 16; i += blockDim.x) {
        int k = i >> 4, c = i & 15;
        int r = k + (k >> 2);
        int pp = ((c >> 2) + r) & 3;
        sW1[(k << 4) + (pp << 2) + (c & 3)] = W1[i];
    }
    __syncthreads();

    const int lane = threadIdx.x & 31;
    const int rv = __brev(lane) >> 27;  // bit-reversed lane = final value index
    const int warp_global = blockIdx.x * (blockDim.x >> 5) + (threadIdx.x >> 5);
    const int nwarps = gridDim.x * (blockDim.x >> 5);

    for (int g = warp_global; g < N_NODES / 4; g += nwarps) {
        const int n0 = g * 4;
        const float* __restrict__ f0 = feat + (size_t)n0 * IN_FEATS;

        unsigned long long v[32];
        #pragma unroll
        for (int i = 0; i < 32; i++) v[i] = 0ull;

        float fa[4], fb[4], fc[4];
        #pragma unroll
        for (int j = 0; j < 4; j++) {
            fa[j] = __ldg(f0 + (size_t)j * IN_FEATS + lane);
            fb[j] = __ldg(f0 + (size_t)j * IN_FEATS + lane + 32);
        }

        for (int k = lane; k < IN_FEATS; k += 32) {
            const int k2 = k + 64;
            if (k2 < IN_FEATS) {
                #pragma unroll
                for (int j = 0; j < 4; j++)
                    fc[j] = __ldg(f0 + (size_t)j * IN_FEATS + k2);
            } else {
                #pragma unroll
                for (int j = 0; j < 4; j++) fc[j] = 0.0f;
            }

            const int kb = k << 4;
            const int r = k + (k >> 2);
            const ulonglong2 u0 = *(const ulonglong2*)&sW1[kb + (((0 + r) & 3) << 2)];
            const ulonglong2 u1 = *(const ulonglong2*)&sW1[kb + (((1 + r) & 3) << 2)];
            const ulonglong2 u2 = *(const ulonglong2*)&sW1[kb + (((2 + r) & 3) << 2)];
            const ulonglong2 u3 = *(const ulonglong2*)&sW1[kb + (((3 + r) & 3) << 2)];

            #pragma unroll
            for (int j = 0; j < 4; j++) {
                const unsigned long long ff = pack2(fa[j], fa[j]);
                FMA2(v[j * 8 + 0], u0.x, ff);
                FMA2(v[j * 8 + 1], u0.y, ff);
                FMA2(v[j * 8 + 2], u1.x, ff);
                FMA2(v[j * 8 + 3], u1.y, ff);
                FMA2(v[j * 8 + 4], u2.x, ff);
                FMA2(v[j * 8 + 5], u2.y, ff);
                FMA2(v[j * 8 + 6], u3.x, ff);
                FMA2(v[j * 8 + 7], u3.y, ff);
            }
            #pragma unroll
            for (int j = 0; j < 4; j++) { fa[j] = fb[j]; fb[j] = fc[j]; }
        }

        #pragma unroll
        for (int round = 0; round < 5; round++) {
            const int m = 1 << round;
            const int h = 16 >> round;
            const bool up = (lane & m) != 0;
            #pragma unroll
            for (int i = 0; i < h; i++) {
                unsigned long long send, keep;
                if (up) { send = v[i];     keep = v[i + h]; }
                else    { send = v[i + h]; keep = v[i]; }
                unsigned long long recv = __shfl_xor_sync(0xffffffffu, send, m);
                ADD2(v[i], keep, recv);
            }
        }

        const int n = n0 + (rv >> 3);
        const int c0 = (rv & 7) << 1;
        unsigned lo, hi;
        asm("mov.b64 {%0, %1}, %2;" : "=r"(lo), "=r"(hi) : "l"(v[0]));
        const float ns = g_norm_src[n];
        float2 o;
        o.x = __uint_as_float(lo) * ns;
        o.y = __uint_as_float(hi) * ns;
        *(float2*)&g_x1[(size_t)n * 16 + c0] = o;
    }
}

// Gather layer 1 (CSR) fused with relu + bias + GEMM2 epilogue.
// One warp per dst node; lane = (edge-slot, quad): one LDG.128 covers 8 edges.
__global__ void gather1_kernel(const float* __restrict__ b1,
                               const float* __restrict__ W2) {
    __shared__ float sW2[16 * 8];  // [k][c2], col 7 zero-padded
    __shared__ float sb1[16];
    for (int i = threadIdx.x; i < 16 * 8; i += blockDim.x) {
        int k = i >> 3, c2 = i & 7;
        sW2[i] = (c2 < OUT) ? W2[k * OUT + c2] : 0.0f;
    }
    if (threadIdx.x < 16) sb1[threadIdx.x] = b1[threadIdx.x];
    __syncthreads();

    const int n = (blockIdx.x * blockDim.x + threadIdx.x) >> 5;
    if (n >= N_NODES) return;
    const int lane = threadIdx.x & 31;
    const int q = lane & 3;       // quad: channels 4q..4q+3
    const int eoff = lane >> 2;   // edge slot 0..7

    const int start = g_row_start[n];
    const int end = start + g_deg_in[n];

    float4 acc = make_float4(0.f, 0.f, 0.f, 0.f);
    for (int e = start + eoff; e < end; e += 8) {
        const int s = g_csr_src[e];
        const float4 v = *(const float4*)&g_x1[(size_t)s * 16 + q * 4];
        acc.x += v.x; acc.y += v.y; acc.z += v.z; acc.w += v.w;
    }
    #pragma unroll
    for (int m = 4; m <= 16; m <<= 1) {
        acc.x += __shfl_xor_sync(0xffffffffu, acc.x, m);
        acc.y += __shfl_xor_sync(0xffffffffu, acc.y, m);
        acc.z += __shfl_xor_sync(0xffffffffu, acc.z, m);
        acc.w += __shfl_xor_sync(0xffffffffu, acc.w, m);
    }

    const float nd = g_norm_dst[n];
    const int c2 = lane & 7;
    float acc2 = 0.0f;
    #pragma unroll
    for (int k = 0; k < 16; k++) {
        const int srcq = k >> 2;
        const int comp = k & 3;
        const float t = (comp == 0) ? acc.x : (comp == 1) ? acc.y
                      : (comp == 2) ? acc.z : acc.w;
        const float sum_k = __shfl_sync(0xffffffffu, t, srcq);
        const float hk = fmaxf(sum_k * nd + sb1[k], 0.0f);
        acc2 += hk * sW2[k * 8 + c2];
    }
    if (lane < 8) {
        const float ns = g_norm_src[n];
        g_x2[(size_t)n * 8 + lane] = (lane < OUT) ? acc2 * ns : 0.0f;
    }
}

// Gather layer 2 fused with final bias. One warp per dst node;
// lane = (edge-slot, half): one LDG.128 covers 16 edges.
__global__ void gather2_kernel(const float* __restrict__ b2,
                               float* __restrict__ out) {
    __shared__ float sb2[8];
    if (threadIdx.x < 8) sb2[threadIdx.x] = (threadIdx.x < OUT) ? b2[threadIdx.x] : 0.0f;
    __syncthreads();

    const int n = (blockIdx.x * blockDim.x + threadIdx.x) >> 5;
    if (n >= N_NODES) return;
    const int lane = threadIdx.x & 31;
    const int half = lane & 1;    // channels 4*half..4*half+3
    const int eoff = lane >> 1;   // edge slot 0..15

    const int start = g_row_start[n];
    const int end = start + g_deg_in[n];

    float4 acc = make_float4(0.f, 0.f, 0.f, 0.f);
    for (int e = start + eoff; e < end; e += 16) {
        const int s = g_csr_src[e];
        const float4 v = *(const float4*)&g_x2[(size_t)s * 8 + half * 4];
        acc.x += v.x; acc.y += v.y; acc.z += v.z; acc.w += v.w;
    }
    #pragma unroll
    for (int m = 2; m <= 16; m <<= 1) {
        acc.x += __shfl_xor_sync(0xffffffffu, acc.x, m);
        acc.y += __shfl_xor_sync(0xffffffffu, acc.y, m);
        acc.z += __shfl_xor_sync(0xffffffffu, acc.z, m);
        acc.w += __shfl_xor_sync(0xffffffffu, acc.w, m);
    }

    if (lane < 2) {
        const float nd = g_norm_dst[n];
        float* o = out + (size_t)n * OUT;
        if (lane == 0) {
            o[0] = acc.x * nd + sb2[0];
            o[1] = acc.y * nd + sb2[1];
            o[2] = acc.z * nd + sb2[2];
            o[3] = acc.w * nd + sb2[3];
        } else {
            o[4] = acc.x * nd + sb2[4];
            o[5] = acc.y * nd + sb2[5];
            o[6] = acc.z * nd + sb2[6];
        }
    }
}

// ---------------- launch ----------------
static cudaStream_t s_side = nullptr;
static cudaEvent_t  s_evFork = nullptr;
static cudaEvent_t  s_evJoin = nullptr;

extern "C" void kernel_launch(void* const* d_in, const int* in_sizes, int n_in,
                              void* d_out, int out_size) {
    const float* feat = (const float*)d_in[0];
    const void*  ei   = d_in[1];
    const float* W1   = (const float*)d_in[2];
    const float* b1   = (const float*)d_in[3];
    const float* W2   = (const float*)d_in[4];
    const float* b2   = (const float*)d_in[5];
    float* out = (float*)d_out;

    const int smem1 = IN_FEATS * 16 * sizeof(float);  // 91712 bytes

    if (s_side == nullptr) {
        cudaStreamCreateWithFlags(&s_side, cudaStreamNonBlocking);
        cudaEventCreateWithFlags(&s_evFork, cudaEventDisableTiming);
        cudaEventCreateWithFlags(&s_evJoin, cudaEventDisableTiming);
        cudaFuncSetAttribute(gemm1_kernel, cudaFuncAttributeMaxDynamicSharedMemorySize, smem1);
    }

    // --- common prefix (legacy stream) ---
    init_kernel<<<NBLK, 256>>>((const int*)ei);
    edge_kernel<<<(N_EDGES / 2 + 255) / 256, 256>>>(ei);
    norm_src_kernel<<<NBLK, 256>>>();

    // --- fork: gemm1 on side stream, CSR build on legacy ---
    cudaEventRecord(s_evFork, 0);
    cudaStreamWaitEvent(s_side, s_evFork, 0);
    gemm1_kernel<<<148, 512, smem1, s_side>>>(feat, W1);
    cudaEventRecord(s_evJoin, s_side);

    scan1_kernel<<<NBLK, 256>>>();
    scan3_kernel<<<NBLK, 256>>>();
    fill_kernel<<<(N_EDGES / 2 + 255) / 256, 256>>>(ei);

    // --- join: gathers need both x1 and CSR ---
    cudaStreamWaitEvent(0, s_evJoin, 0);
    gather1_kernel<<<(N_NODES * 32 + 255) / 256, 256>>>(b1, W2);
    gather2_kernel<<<(N_NODES * 32 + 255) / 256, 256>>>(b2, out);
}

// round 15
// speedup vs baseline: 1.1808x; 1.0776x over previous
#include <cuda_runtime.h>
#include <cuda_bf16.h>
#include <cstdint>

#define N_NODES 100000
#define N_EDGES 3200000
#define IN_FEATS 1433
#define HID 16
#define OUT 7
#define NBLK 391   // ceil(100000/256)
#define NJOB 25000 // N_NODES / 4
#define KVEC 1408  // 11 * 128 vectorized k's per job

// ---------------- device scratch ----------------
__device__ int   g_is64;
__device__ int   g_deg_out[N_NODES];
__device__ int   g_deg_in[N_NODES];
__device__ float g_norm_src[N_NODES];
__device__ float g_norm_dst[N_NODES];
__device__ int   g_row_start[N_NODES];
__device__ int   g_cursor[N_NODES];
__device__ int   g_csr_src[N_EDGES];
__device__ int   g_part[512];
__device__ __align__(128) float g_x1[N_NODES * 16];
__device__ __align__(128) float g_x2[N_NODES * 8];

// ---------------- helpers ----------------
#define FMA2(d, a, b) asm("fma.rn.f32x2 %0, %1, %2, %3;" : "=l"(d) : "l"(a), "l"(b), "l"(d))
#define ADD2(d, a, b) asm("add.rn.f32x2 %0, %1, %2;" : "=l"(d) : "l"(a), "l"(b))

__device__ __forceinline__ unsigned long long pack2(float a, float b) {
    unsigned long long r;
    asm("mov.b64 %0, {%1, %2};" : "=l"(r) : "r"(__float_as_uint(a)), "r"(__float_as_uint(b)));
    return r;
}

// W1 smem swizzle for the float4-k access pattern (k = a + 128c + 4*lane + i):
//  - rows pair-swapped by parity' = (k ^ (k>>2)) & 1  (alternates with lane)
//  - quads rotated by rot = (k>>3) & 3                (distinct among same-parity lanes)
// => all 8 lanes of each LDS.128 phase hit distinct 16B bank-quads.
__device__ __forceinline__ int w_base(int k) {
    return ((k >> 1) << 5) | (((k ^ (k >> 2)) & 1) << 4);
}
__device__ __forceinline__ int w_rot(int k) { return (k >> 3) & 3; }

// ---------------- kernels ----------------

// Zero degree counters + detect int64 vs int32 edge buffer.
__global__ void init_kernel(const int* ei_words) {
    int i = blockIdx.x * blockDim.x + threadIdx.x;
    if (i < N_NODES) { g_deg_out[i] = 0; g_deg_in[i] = 0; }
    if (i == 0) {
        int all_zero = 1;
        for (int t = 0; t < 64; t++)
            if (ei_words[2 * t + 1] != 0) { all_zero = 0; break; }
        g_is64 = all_zero;
    }
}

// Degree histograms, 2 edges per thread (vector loads).
__global__ void edge_kernel(const void* ei_raw) {
    int e0 = (blockIdx.x * blockDim.x + threadIdx.x) * 2;
    if (e0 >= N_EDGES) return;
    int s0, s1, d0, d1;
    if (g_is64) {
        const longlong2 sv = *(const longlong2*)((const long long*)ei_raw + e0);
        const longlong2 dv = *(const longlong2*)((const long long*)ei_raw + N_EDGES + e0);
        s0 = (int)sv.x; s1 = (int)sv.y; d0 = (int)dv.x; d1 = (int)dv.y;
    } else {
        const int2 sv = *(const int2*)((const int*)ei_raw + e0);
        const int2 dv = *(const int2*)((const int*)ei_raw + N_EDGES + e0);
        s0 = sv.x; s1 = sv.y; d0 = dv.x; d1 = dv.y;
    }
    atomicAdd(&g_deg_out[s0], 1);
    atomicAdd(&g_deg_out[s1], 1);
    atomicAdd(&g_deg_in[d0], 1);
    atomicAdd(&g_deg_in[d1], 1);
}

// norm_src only (unblocks gemm1 on the side stream).
__global__ void norm_src_kernel() {
    int i = blockIdx.x * blockDim.x + threadIdx.x;
    if (i >= N_NODES) return;
    int dout = g_deg_out[i]; if (dout < 1) dout = 1;
    g_norm_src[i] = rsqrtf((float)dout);
}

// scan pass 1: per-block sums of deg_in
__global__ void scan1_kernel() {
    __shared__ int s[256];
    int tid = threadIdx.x;
    int i = blockIdx.x * 256 + tid;
    s[tid] = (i < N_NODES) ? g_deg_in[i] : 0;
    __syncthreads();
    for (int off = 128; off > 0; off >>= 1) {
        if (tid < off) s[tid] += s[tid + off];
        __syncthreads();
    }
    if (tid == 0) g_part[blockIdx.x] = s[0];
}

// scan pass 2+3 fused: each block redundantly reduces its prefix of g_part,
// then does the intra-block scan + row_start/cursor/norm_dst writes.
__global__ void scan3_kernel() {
    __shared__ int s[256];
    __shared__ int sp[256];
    __shared__ int sbase;
    int tid = threadIdx.x;

    int p = 0;
    for (int t = tid; t < blockIdx.x; t += 256) p += g_part[t];
    sp[tid] = p;
    __syncthreads();
    for (int off = 128; off > 0; off >>= 1) {
        if (tid < off) sp[tid] += sp[tid + off];
        __syncthreads();
    }
    if (tid == 0) sbase = sp[0];
    __syncthreads();

    int i = blockIdx.x * 256 + tid;
    int v = (i < N_NODES) ? g_deg_in[i] : 0;
    s[tid] = v;
    __syncthreads();
    for (int off = 1; off < 256; off <<= 1) {
        int t = (tid >= off) ? s[tid - off] : 0;
        __syncthreads();
        s[tid] += t;
        __syncthreads();
    }
    if (i < N_NODES) {
        int rs = sbase + s[tid] - v;
        g_row_start[i] = rs;
        g_cursor[i] = rs;
        int din = g_deg_in[i]; if (din < 1) din = 1;
        g_norm_dst[i] = rsqrtf((float)din);
    }
}

// Fill CSR (grouped by dst, storing src ids), 2 edges per thread.
__global__ void fill_kernel(const void* ei_raw) {
    int e0 = (blockIdx.x * blockDim.x + threadIdx.x) * 2;
    if (e0 >= N_EDGES) return;
    int s0, s1, d0, d1;
    if (g_is64) {
        const longlong2 sv = *(const longlong2*)((const long long*)ei_raw + e0);
        const longlong2 dv = *(const longlong2*)((const long long*)ei_raw + N_EDGES + e0);
        s0 = (int)sv.x; s1 = (int)sv.y; d0 = (int)dv.x; d1 = (int)dv.y;
    } else {
        const int2 sv = *(const int2*)((const int*)ei_raw + e0);
        const int2 dv = *(const int2*)((const int*)ei_raw + N_EDGES + e0);
        s0 = sv.x; s1 = sv.y; d0 = dv.x; d1 = dv.y;
    }
    int p0 = atomicAdd(&g_cursor[d0], 1);
    g_csr_src[p0] = s0;
    int p1 = atomicAdd(&g_cursor[d1], 1);
    g_csr_src[p1] = s1;
}

// GEMM1: x1[n, :] = norm_src[n] * (feat[n, :] @ W1)
// Warp handles nodes {g, g+25000, g+50000, g+75000} — all share feat-row
// alignment class, enabling aligned float4 (LDG.128) feat loads from
// k = a = (-g)&3. 11 chunks of 128 k's + 25-k scalar epilogue.
// f32x2 FMA, double-buffered chunk prefetch, merged transpose-reduce.
__global__ void __launch_bounds__(512, 1) gemm1_kernel(const float* __restrict__ feat,
                                                       const float* __restrict__ W1) {
    extern __shared__ float sW1[];  // 1434*16 floats, swizzled
    for (int i = threadIdx.x; i < IN_FEATS * 16; i += blockDim.x) {
        int k = i >> 4, c = i & 15;
        int pp = ((c >> 2) + w_rot(k)) & 3;
        sW1[w_base(k) + (pp << 2) + (c & 3)] = W1[i];
    }
    __syncthreads();

    const int lane = threadIdx.x & 31;
    const int rv = __brev(lane) >> 27;  // bit-reversed lane = final value index
    const int warp_global = blockIdx.x * (blockDim.x >> 5) + (threadIdx.x >> 5);
    const int nwarps = gridDim.x * (blockDim.x >> 5);

    for (int g = warp_global; g < NJOB; g += nwarps) {
        const int a = (4 - (g & 3)) & 3;  // shared alignment offset for this warp's rows

        const float* __restrict__ p0 = feat + (size_t)g * IN_FEATS;
        const float* __restrict__ p1 = p0 + (size_t)NJOB * IN_FEATS;
        const float* __restrict__ p2 = p1 + (size_t)NJOB * IN_FEATS;
        const float* __restrict__ p3 = p2 + (size_t)NJOB * IN_FEATS;

        // v[j*8+p] = f32x2 partial for node j, channels (2p, 2p+1)
        unsigned long long v[32];
        #pragma unroll
        for (int i = 0; i < 32; i++) v[i] = 0ull;

        const int kb0 = a + (lane << 2);
        float4 fcur[4], fnext[4];
        fcur[0] = __ldg((const float4*)(p0 + kb0));
        fcur[1] = __ldg((const float4*)(p1 + kb0));
        fcur[2] = __ldg((const float4*)(p2 + kb0));
        fcur[3] = __ldg((const float4*)(p3 + kb0));

        for (int c = 0; c < 11; c++) {
            const int kbase = kb0 + c * 128;  // lane's k for i=0
            if (c < 10) {
                const int kn = kbase + 128;
                fnext[0] = __ldg((const float4*)(p0 + kn));
                fnext[1] = __ldg((const float4*)(p1 + kn));
                fnext[2] = __ldg((const float4*)(p2 + kn));
                fnext[3] = __ldg((const float4*)(p3 + kn));
            }

            #pragma unroll
            for (int i = 0; i < 4; i++) {
                const int k = kbase + i;
                const int bf = w_base(k);
                const int rot = w_rot(k);
                const ulonglong2 u0 = *(const ulonglong2*)&sW1[bf + (((0 + rot) & 3) << 2)];
                const ulonglong2 u1 = *(const ulonglong2*)&sW1[bf + (((1 + rot) & 3) << 2)];
                const ulonglong2 u2 = *(const ulonglong2*)&sW1[bf + (((2 + rot) & 3) << 2)];
                const ulonglong2 u3 = *(const ulonglong2*)&sW1[bf + (((3 + rot) & 3) << 2)];

                #pragma unroll
                for (int j = 0; j < 4; j++) {
                    const float f = (i == 0) ? fcur[j].x : (i == 1) ? fcur[j].y
                                  : (i == 2) ? fcur[j].z : fcur[j].w;
                    const unsigned long long ff = pack2(f, f);
                    FMA2(v[j * 8 + 0], u0.x, ff);
                    FMA2(v[j * 8 + 1], u0.y, ff);
                    FMA2(v[j * 8 + 2], u1.x, ff);
                    FMA2(v[j * 8 + 3], u1.y, ff);
                    FMA2(v[j * 8 + 4], u2.x, ff);
                    FMA2(v[j * 8 + 5], u2.y, ff);
                    FMA2(v[j * 8 + 6], u3.x, ff);
                    FMA2(v[j * 8 + 7], u3.y, ff);
                }
            }
            if (c < 10) {
                #pragma unroll
                for (int j = 0; j < 4; j++) fcur[j] = fnext[j];
            }
        }

        // Scalar epilogue: the 25 k's outside [a, a+1408): head [0,a) + tail.
        if (lane < 25) {
            const int k = (lane < a) ? lane : KVEC + lane;
            const int bf = w_base(k);
            const int rot = w_rot(k);
            const ulonglong2 u0 = *(const ulonglong2*)&sW1[bf + (((0 + rot) & 3) << 2)];
            const ulonglong2 u1 = *(const ulonglong2*)&sW1[bf + (((1 + rot) & 3) << 2)];
            const ulonglong2 u2 = *(const ulonglong2*)&sW1[bf + (((2 + rot) & 3) << 2)];
            const ulonglong2 u3 = *(const ulonglong2*)&sW1[bf + (((3 + rot) & 3) << 2)];
            const float fs[4] = { __ldg(p0 + k), __ldg(p1 + k), __ldg(p2 + k), __ldg(p3 + k) };
            #pragma unroll
            for (int j = 0; j < 4; j++) {
                const unsigned long long ff = pack2(fs[j], fs[j]);
                FMA2(v[j * 8 + 0], u0.x, ff);
                FMA2(v[j * 8 + 1], u0.y, ff);
                FMA2(v[j * 8 + 2], u1.x, ff);
                FMA2(v[j * 8 + 3], u1.y, ff);
                FMA2(v[j * 8 + 4], u2.x, ff);
                FMA2(v[j * 8 + 5], u2.y, ff);
                FMA2(v[j * 8 + 6], u3.x, ff);
                FMA2(v[j * 8 + 7], u3.y, ff);
            }
        }

        // Merged transpose-reduce: lane ends holding value index bitrev(lane).
        #pragma unroll
        for (int round = 0; round < 5; round++) {
            const int m = 1 << round;
            const int h = 16 >> round;
            const bool up = (lane & m) != 0;
            #pragma unroll
            for (int i = 0; i < h; i++) {
                unsigned long long send, keep;
                if (up) { send = v[i];     keep = v[i + h]; }
                else    { send = v[i + h]; keep = v[i]; }
                unsigned long long recv = __shfl_xor_sync(0xffffffffu, send, m);
                ADD2(v[i], keep, recv);
            }
        }

        const int n = g + NJOB * (rv >> 3);
        const int c0 = (rv & 7) << 1;
        unsigned lo, hi;
        asm("mov.b64 {%0, %1}, %2;" : "=r"(lo), "=r"(hi) : "l"(v[0]));
        const float ns = g_norm_src[n];
        float2 o;
        o.x = __uint_as_float(lo) * ns;
        o.y = __uint_as_float(hi) * ns;
        *(float2*)&g_x1[(size_t)n * 16 + c0] = o;
    }
}

// Gather layer 1 (CSR) fused with relu + bias + GEMM2 epilogue.
// One warp per dst node; lane = (edge-slot, quad): one LDG.128 covers 8 edges.
__global__ void gather1_kernel(const float* __restrict__ b1,
                               const float* __restrict__ W2) {
    __shared__ float sW2[16 * 8];  // [k][c2], col 7 zero-padded
    __shared__ float sb1[16];
    for (int i = threadIdx.x; i < 16 * 8; i += blockDim.x) {
        int k = i >> 3, c2 = i & 7;
        sW2[i] = (c2 < OUT) ? W2[k * OUT + c2] : 0.0f;
    }
    if (threadIdx.x < 16) sb1[threadIdx.x] = b1[threadIdx.x];
    __syncthreads();

    const int n = (blockIdx.x * blockDim.x + threadIdx.x) >> 5;
    if (n >= N_NODES) return;
    const int lane = threadIdx.x & 31;
    const int q = lane & 3;       // quad: channels 4q..4q+3
    const int eoff = lane >> 2;   // edge slot 0..7

    const int start = g_row_start[n];
    const int end = start + g_deg_in[n];

    float4 acc = make_float4(0.f, 0.f, 0.f, 0.f);
    for (int e = start + eoff; e < end; e += 8) {
        const int s = g_csr_src[e];
        const float4 v = *(const float4*)&g_x1[(size_t)s * 16 + q * 4];
        acc.x += v.x; acc.y += v.y; acc.z += v.z; acc.w += v.w;
    }
    #pragma unroll
    for (int m = 4; m <= 16; m <<= 1) {
        acc.x += __shfl_xor_sync(0xffffffffu, acc.x, m);
        acc.y += __shfl_xor_sync(0xffffffffu, acc.y, m);
        acc.z += __shfl_xor_sync(0xffffffffu, acc.z, m);
        acc.w += __shfl_xor_sync(0xffffffffu, acc.w, m);
    }

    const float nd = g_norm_dst[n];
    const int c2 = lane & 7;
    float acc2 = 0.0f;
    #pragma unroll
    for (int k = 0; k < 16; k++) {
        const int srcq = k >> 2;
        const int comp = k & 3;
        const float t = (comp == 0) ? acc.x : (comp == 1) ? acc.y
                      : (comp == 2) ? acc.z : acc.w;
        const float sum_k = __shfl_sync(0xffffffffu, t, srcq);
        const float hk = fmaxf(sum_k * nd + sb1[k], 0.0f);
        acc2 += hk * sW2[k * 8 + c2];
    }
    if (lane < 8) {
        const float ns = g_norm_src[n];
        g_x2[(size_t)n * 8 + lane] = (lane < OUT) ? acc2 * ns : 0.0f;
    }
}

// Gather layer 2 fused with final bias. One warp per dst node;
// lane = (edge-slot, half): one LDG.128 covers 16 edges.
__global__ void gather2_kernel(const float* __restrict__ b2,
                               float* __restrict__ out) {
    __shared__ float sb2[8];
    if (threadIdx.x < 8) sb2[threadIdx.x] = (threadIdx.x < OUT) ? b2[threadIdx.x] : 0.0f;
    __syncthreads();

    const int n = (blockIdx.x * blockDim.x + threadIdx.x) >> 5;
    if (n >= N_NODES) return;
    const int lane = threadIdx.x & 31;
    const int half = lane & 1;    // channels 4*half..4*half+3
    const int eoff = lane >> 1;   // edge slot 0..15

    const int start = g_row_start[n];
    const int end = start + g_deg_in[n];

    float4 acc = make_float4(0.f, 0.f, 0.f, 0.f);
    for (int e = start + eoff; e < end; e += 16) {
        const int s = g_csr_src[e];
        const float4 v = *(const float4*)&g_x2[(size_t)s * 8 + half * 4];
        acc.x += v.x; acc.y += v.y; acc.z += v.z; acc.w += v.w;
    }
    #pragma unroll
    for (int m = 2; m <= 16; m <<= 1) {
        acc.x += __shfl_xor_sync(0xffffffffu, acc.x, m);
        acc.y += __shfl_xor_sync(0xffffffffu, acc.y, m);
        acc.z += __shfl_xor_sync(0xffffffffu, acc.z, m);
        acc.w += __shfl_xor_sync(0xffffffffu, acc.w, m);
    }

    if (lane < 2) {
        const float nd = g_norm_dst[n];
        float* o = out + (size_t)n * OUT;
        if (lane == 0) {
            o[0] = acc.x * nd + sb2[0];
            o[1] = acc.y * nd + sb2[1];
            o[2] = acc.z * nd + sb2[2];
            o[3] = acc.w * nd + sb2[3];
        } else {
            o[4] = acc.x * nd + sb2[4];
            o[5] = acc.y * nd + sb2[5];
            o[6] = acc.z * nd + sb2[6];
        }
    }
}

// ---------------- launch ----------------
static cudaStream_t s_side = nullptr;
static cudaEvent_t  s_evFork = nullptr;
static cudaEvent_t  s_evJoin = nullptr;

extern "C" void kernel_launch(void* const* d_in, const int* in_sizes, int n_in,
                              void* d_out, int out_size) {
    const float* feat = (const float*)d_in[0];
    const void*  ei   = d_in[1];
    const float* W1   = (const float*)d_in[2];
    const float* b1   = (const float*)d_in[3];
    const float* W2   = (const float*)d_in[4];
    const float* b2   = (const float*)d_in[5];
    float* out = (float*)d_out;

    const int smem1 = 1434 * 16 * sizeof(float);  // 91776 bytes (1 pad row)

    if (s_side == nullptr) {
        cudaStreamCreateWithFlags(&s_side, cudaStreamNonBlocking);
        cudaEventCreateWithFlags(&s_evFork, cudaEventDisableTiming);
        cudaEventCreateWithFlags(&s_evJoin, cudaEventDisableTiming);
        cudaFuncSetAttribute(gemm1_kernel, cudaFuncAttributeMaxDynamicSharedMemorySize, smem1);
    }

    // --- common prefix (legacy stream) ---
    init_kernel<<<NBLK, 256>>>((const int*)ei);
    edge_kernel<<<(N_EDGES / 2 + 255) / 256, 256>>>(ei);
    norm_src_kernel<<<NBLK, 256>>>();

    // --- fork: gemm1 on side stream, CSR build on legacy ---
    cudaEventRecord(s_evFork, 0);
    cudaStreamWaitEvent(s_side, s_evFork, 0);
    gemm1_kernel<<<148, 512, smem1, s_side>>>(feat, W1);
    cudaEventRecord(s_evJoin, s_side);

    scan1_kernel<<<NBLK, 256>>>();
    scan3_kernel<<<NBLK, 256>>>();
    fill_kernel<<<(N_EDGES / 2 + 255) / 256, 256>>>(ei);

    // --- join: gathers need both x1 and CSR ---
    cudaStreamWaitEvent(0, s_evJoin, 0);
    gather1_kernel<<<(N_NODES * 32 + 255) / 256, 256>>>(b1, W2);
    gather2_kernel<<<(N_NODES * 32 + 255) / 256, 256>>>(b2, out);
}